// round 14
// baseline (speedup 1.0000x reference)
#include <cuda_runtime.h>
#include <math.h>

#define NSTEPS 130
#define NLUT   27

// srcA[l] / srcB[l]: flat-state index feeding mux selects A / B of LUT-lane l.
// Lanes 27..31 are constant-carrier lanes (self-wired).
__device__ __constant__ int c_srcA[32] = {
    1, 3, 3,   7, 0, 0,   4, 6, 6,   19, 12, 12,  16, 9, 9,
    13, 15, 15, 10, 18, 18, 22, 6, 6, 25, 15, 15,
    27, 28, 29, 30, 31};
__device__ __constant__ int c_srcB[32] = {
    17, 17, 1,  5, 5, 7,   11, 11, 4, 8, 8, 19,   28, 28, 16,
    2, 2, 13,   27, 27, 10, 23, 23, 22, 26, 26, 25,
    27, 28, 29, 30, 31};

__global__ void one_layer_net_kernel(const float* __restrict__ x,
                                     const float* __restrict__ weights,
                                     const float4* __restrict__ noise4,
                                     float* __restrict__ out) {
    const int lane = threadIdx.x & 31;
    const bool act = (lane < NLUT);
    const int  nl  = act ? lane : 0;
    const int  sa  = c_srcA[lane];
    const int  sb  = c_srcB[lane];

    // Register ring of noise (depth 8): prefetch distance ~8 steps
    // (~350 cyc) covers L2-hot latency (~250 cyc). Noise is 56KB, resident
    // in L2 across graph replays.
    float4 nb[8];
#pragma unroll
    for (int j = 0; j < 8; ++j)
        nb[j] = noise4[j * NLUT + nl];

    // Per-lane constants. Quadruple (u,v,r,s) is linear in the 4 noise
    // values: w_i = wb_i + c_i*n_i with c_i = |1-|wb_i||*0.125, and
    //   u = 0.25( w0-w1-w2+w3), v = 0.25(-w0-w1+w2+w3),
    //   r = 0.25(-w0+w1-w2+w3), s = 0.25( w0+w1+w2+w3).
    // Fold 0.25 into e_i = 0.25*c_i and the bias into u0..s0.
    float4 wb = make_float4(0.f, 0.f, 0.f, 0.f);
    if (act) wb = reinterpret_cast<const float4*>(weights)[lane];
    float e0 = fabsf(1.0f - fabsf(wb.x)) * 0.03125f;   // 0.125*0.25
    float e1 = fabsf(1.0f - fabsf(wb.y)) * 0.03125f;
    float e2 = fabsf(1.0f - fabsf(wb.z)) * 0.03125f;
    float e3 = fabsf(1.0f - fabsf(wb.w)) * 0.03125f;
    float u0 = 0.25f * ( wb.x - wb.y - wb.z + wb.w);
    float v0 = 0.25f * (-wb.x - wb.y + wb.z + wb.w);
    float r0 = 0.25f * (-wb.x + wb.y - wb.z + wb.w);
    float s0 = 0.25f * ( wb.x + wb.y + wb.z + wb.w);

    const float xv = (lane == 27) ? x[0] : ((lane == 28) ? x[1] : 0.0f);
    if (!act) { e0 = e1 = e2 = e3 = 0.f; u0 = v0 = r0 = 0.f; s0 = xv; }

    float state = act ? -1.0f : xv;   // lanes 29..31: xv = 0

#define STEP(k, slot, prefetch)                                              \
    do {                                                                     \
        const float4 n = nb[slot];                                           \
        if (prefetch) {                                                      \
            const int pi = ((k) + 8 < NSTEPS) ? ((k) + 8) : (NSTEPS - 1);    \
            nb[slot] = noise4[pi * NLUT + nl];                               \
        }                                                                    \
        const float A = __shfl_sync(0xFFFFFFFFu, state, sa);                 \
        const float B = __shfl_sync(0xFFFFFFFFu, state, sb);                 \
        const float t0 = e0 * n.x, t1 = e1 * n.y;                            \
        const float t2 = e2 * n.z, t3 = e3 * n.w;                            \
        const float m = t0 - t1, p = t0 + t1;                                \
        const float M = t2 - t3, P = t2 + t3;                                \
        const float u = u0 + (m - M);                                        \
        const float v = v0 + (P - p);                                        \
        const float r = r0 - (m + M);                                        \
        const float s = s0 + (p + P);                                        \
        state = fmaf(B, fmaf(A, u, v), fmaf(A, r, s));                       \
    } while (0)

    // 16 chunks of 8 steps (slot index compile-time constant inside).
#pragma unroll 1
    for (int k0 = 0; k0 < 128; k0 += 8) {
#pragma unroll
        for (int j = 0; j < 8; ++j)
            STEP(k0 + j, j, 1);
    }
    // Tail: steps 128, 129 (slots 0, 1; no prefetch).
    STEP(128, 0, 0);
    STEP(129, 1, 0);

    // Outputs: final[0,1] -> flat 1, final[1,2] -> flat 5, final[7,2] -> flat 23.
    if (lane == 1)  out[0] = state;
    if (lane == 5)  out[1] = state;
    if (lane == 23) out[2] = state;
}

extern "C" void kernel_launch(void* const* d_in, const int* in_sizes, int n_in,
                              void* d_out, int out_size) {
    (void)in_sizes; (void)n_in; (void)out_size;
    const float*  x  = (const float*)d_in[0];      // [2]
    const float*  w  = (const float*)d_in[1];      // [9,3,4]
    const float4* nz = (const float4*)d_in[2];     // [130,9,3,4] as float4
    float* out = (float*)d_out;                    // [3]

    // Single warp, no shared memory, no launch attributes.
    one_layer_net_kernel<<<1, 32>>>(x, w, nz, out);
}

// round 15
// speedup vs baseline: 1.4588x; 1.4588x over previous
#include <cuda_runtime.h>
#include <math.h>

#define NSTEPS 130
#define NLUT   27
#define ROWS   32
#define UROWS  132          // 130 data rows + 2 padding rows for tail prefetch

// srcA[l] / srcB[l]: flat-state index feeding mux selects A / B of LUT-lane l.
// Lanes 27..31 are constant-carrier lanes (self-wired).
__device__ __constant__ int c_srcA[32] = {
    1, 3, 3,   7, 0, 0,   4, 6, 6,   19, 12, 12,  16, 9, 9,
    13, 15, 15, 10, 18, 18, 22, 6, 6, 25, 15, 15,
    27, 28, 29, 30, 31};
__device__ __constant__ int c_srcB[32] = {
    17, 17, 1,  5, 5, 7,   11, 11, 4, 8, 8, 19,   28, 28, 16,
    2, 2, 13,   27, 27, 10, 23, 23, 22, 26, 26, 25,
    27, 28, 29, 30, 31};

#define BAR_ARRIVE(b) asm volatile("bar.arrive %0, 64;" :: "r"(b) : "memory")
#define BAR_WAIT(b)   asm volatile("bar.sync %0, 64;"   :: "r"(b) : "memory")

__global__ void one_layer_net_kernel(const float* __restrict__ x,
                                     const float* __restrict__ weights,
                                     const float4* __restrict__ noise4,
                                     float* __restrict__ out) {
    extern __shared__ float4 s_uvrs[];   // [132][32] quadruples

    const int tid  = threadIdx.x;
    const int wrp  = tid >> 5;
    const int lane = tid & 31;

    // Warps 4 and 8 exit immediately: SMSP0 (wid%4==0) belongs exclusively
    // to the consumer warp 0 for the whole kernel.
    if (wrp == 4 || wrp == 8) return;

    if (wrp > 0) {
        // ----------- PRODUCER WARPS {1,2,3,5,6,7,9} (R7 layout) ------------
        const bool act = (lane < NLUT);
        const int  nl  = act ? lane : 0;

        // Compact producer index 0..5 for the six 20-row warps.
        // w2->0, w3->1, w5->2, w6->3, w7->4, w9->5
        const int pidx = (wrp == 2) ? 0 : (wrp == 3) ? 1 : (wrp == 5) ? 2
                       : (wrp == 6) ? 3 : (wrp == 7) ? 4 : 5;

        // warp1 -> rows 0..5 then 126..131; others -> 20 rows each.
        const int s0 = (wrp == 1) ? 0 : 6 + 20 * pidx;
        const int nrows = (wrp == 1) ? 6 : 20;

        // Front-batch noise loads (max MLP) BEFORE the weights load.
        float4 nbuf[20];
#pragma unroll
        for (int i = 0; i < 20; ++i)
            if (i < nrows) nbuf[i] = noise4[(s0 + i) * NLUT + nl];

        float4 wb = make_float4(0.f, 0.f, 0.f, 0.f);
        if (act) wb = reinterpret_cast<const float4*>(weights)[lane];
        const float c0 = fabsf(1.0f - fabsf(wb.x)) * 0.125f;
        const float c1 = fabsf(1.0f - fabsf(wb.y)) * 0.125f;
        const float c2 = fabsf(1.0f - fabsf(wb.z)) * 0.125f;
        const float c3 = fabsf(1.0f - fabsf(wb.w)) * 0.125f;
        const float xv = (lane == 27) ? x[0] : ((lane == 28) ? x[1] : 0.0f);

#pragma unroll
        for (int i = 0; i < 20; ++i) {
            if (i >= nrows) break;
            const float4 n = nbuf[i];
            const float w0 = fmaf(c0, n.x, wb.x);
            const float w1 = fmaf(c1, n.y, wb.y);
            const float w2 = fmaf(c2, n.z, wb.z);
            const float w3 = fmaf(c3, n.w, wb.w);
            const float d01 = w1 - w0, d23 = w3 - w2;
            const float p01 = w0 + w1, p23 = w2 + w3;
            float4 q;
            q.x = act ? 0.25f * (d23 - d01) : 0.f;
            q.y = act ? 0.25f * (p23 - p01) : 0.f;
            q.z = act ? 0.25f * (d01 + d23) : 0.f;
            q.w = act ? 0.25f * (p01 + p23) : xv;
            s_uvrs[(s0 + i) * ROWS + lane] = q;
        }
        // Barrier: warp1 -> bar1; 20-row producers -> bars 2..7.
        {
            int b = (wrp == 1) ? 1 : (2 + pidx);
            BAR_ARRIVE(b);
        }

        if (wrp == 1) {
            // Second pass: rows 126..129 real, 130..131 zero padding.
            float4 nb2[4];
#pragma unroll
            for (int i = 0; i < 4; ++i)
                nb2[i] = noise4[(126 + i) * NLUT + nl];
#pragma unroll
            for (int i = 0; i < 4; ++i) {
                const float4 n = nb2[i];
                const float w0 = fmaf(c0, n.x, wb.x);
                const float w1 = fmaf(c1, n.y, wb.y);
                const float w2 = fmaf(c2, n.z, wb.z);
                const float w3 = fmaf(c3, n.w, wb.w);
                const float d01 = w1 - w0, d23 = w3 - w2;
                const float p01 = w0 + w1, p23 = w2 + w3;
                float4 q;
                q.x = act ? 0.25f * (d23 - d01) : 0.f;
                q.y = act ? 0.25f * (p23 - p01) : 0.f;
                q.z = act ? 0.25f * (d01 + d23) : 0.f;
                q.w = act ? 0.25f * (p01 + p23) : xv;
                s_uvrs[(126 + i) * ROWS + lane] = q;
            }
            s_uvrs[130 * ROWS + lane] = make_float4(0.f, 0.f, 0.f, 0.f);
            s_uvrs[131 * ROWS + lane] = make_float4(0.f, 0.f, 0.f, 0.f);
            int b8 = 8;
            BAR_ARRIVE(b8);
        }
        return;
    }

    // ----------------------- CONSUMER WARP (0) — R7 scan -------------------
    const int sa = c_srcA[lane];
    const int sb = c_srcB[lane];
    const int aa = c_srcA[sa], ba = c_srcB[sa];
    const int ab = c_srcA[sb], bb = c_srcB[sb];

    float state = (lane < NLUT) ? -1.0f
                : (lane == 27) ? x[0]
                : (lane == 28) ? x[1] : 0.0f;

    int b = 1;
    BAR_WAIT(b);   // rows 0..5 ready

    const float4* pAp = s_uvrs + sa;
    const float4* pBp = s_uvrs + sb;
    const float4* pFp = s_uvrs + ROWS + lane;
    float4 cA = pAp[0];
    float4 cB = pBp[0];
    float4 cF = pFp[0];
    pAp += 2 * ROWS; pBp += 2 * ROWS; pFp += 2 * ROWS;

#define SCAN_ITER()                                                          \
    do {                                                                     \
        const float4 pA = pAp[0];                                            \
        const float4 pB = pBp[0];                                            \
        const float4 pF = pFp[0];                                            \
        pAp += 2 * ROWS; pBp += 2 * ROWS; pFp += 2 * ROWS;                   \
        const float aAv = __shfl_sync(0xFFFFFFFFu, state, aa);               \
        const float bAv = __shfl_sync(0xFFFFFFFFu, state, ba);               \
        const float aBv = __shfl_sync(0xFFFFFFFFu, state, ab);               \
        const float bBv = __shfl_sync(0xFFFFFFFFu, state, bb);               \
        const float iA = fmaf(bAv, fmaf(aAv, cA.x, cA.y),                    \
                              fmaf(aAv, cA.z, cA.w));                        \
        const float iB = fmaf(bBv, fmaf(aBv, cB.x, cB.y),                    \
                              fmaf(aBv, cB.z, cB.w));                        \
        state = fmaf(iB, fmaf(iA, cF.x, cF.y), fmaf(iA, cF.z, cF.w));        \
        cA = pA; cB = pB; cF = pF;                                           \
    } while (0)

    // iter k consumes rows 2k,2k+1 and prefetches rows 2k+2,2k+3
    // (needs rows <= 2k+3):
    //   k=0..1    <=5    (bar1, passed)
    //   k=2..11   <=25   (bar2: w2)     k=12..21 <=45  (bar3: w3)
    //   k=22..31  <=65   (bar4: w5)     k=32..41 <=85  (bar5: w6)
    //   k=42..51  <=105  (bar6: w7)     k=52..61 <=125 (bar7: w9)
    //   k=62..64  <=131  (bar8: w1 pass 2 + pads)
    SCAN_ITER();
    SCAN_ITER();
#pragma unroll
    for (int seg = 0; seg < 6; ++seg) {
        b = 2 + seg;
        BAR_WAIT(b);
#pragma unroll
        for (int i = 0; i < 10; ++i) SCAN_ITER();
    }
    b = 8;
    BAR_WAIT(b);
    SCAN_ITER();
    SCAN_ITER();
    SCAN_ITER();

    // Outputs: final[0,1] -> flat 1, final[1,2] -> flat 5, final[7,2] -> flat 23.
    if (lane == 1)  out[0] = state;
    if (lane == 5)  out[1] = state;
    if (lane == 23) out[2] = state;
}

extern "C" void kernel_launch(void* const* d_in, const int* in_sizes, int n_in,
                              void* d_out, int out_size) {
    (void)in_sizes; (void)n_in; (void)out_size;
    const float*  x  = (const float*)d_in[0];      // [2]
    const float*  w  = (const float*)d_in[1];      // [9,3,4]
    const float4* nz = (const float4*)d_in[2];     // [130,9,3,4] as float4
    float* out = (float*)d_out;                    // [3]

    const size_t smem = (size_t)UROWS * ROWS * sizeof(float4);   // 67584 B
    cudaFuncSetAttribute(one_layer_net_kernel,
                         cudaFuncAttributeMaxDynamicSharedMemorySize, (int)smem);
    one_layer_net_kernel<<<1, 320, smem>>>(x, w, nz, out);
}

// round 16
// speedup vs baseline: 1.5018x; 1.0295x over previous
#include <cuda_runtime.h>
#include <math.h>

#define NSTEPS 130
#define NLUT   27
#define ROWS   32
#define UROWS  132          // 130 data rows + 2 padding rows for tail prefetch

// srcA[l] / srcB[l]: flat-state index feeding mux selects A / B of LUT-lane l.
// Lanes 27..31 are constant-carrier lanes (self-wired).
__device__ __constant__ int c_srcA[32] = {
    1, 3, 3,   7, 0, 0,   4, 6, 6,   19, 12, 12,  16, 9, 9,
    13, 15, 15, 10, 18, 18, 22, 6, 6, 25, 15, 15,
    27, 28, 29, 30, 31};
__device__ __constant__ int c_srcB[32] = {
    17, 17, 1,  5, 5, 7,   11, 11, 4, 8, 8, 19,   28, 28, 16,
    2, 2, 13,   27, 27, 10, 23, 23, 22, 26, 26, 25,
    27, 28, 29, 30, 31};

#define BAR_ARRIVE(b) asm volatile("bar.arrive %0, 64;" :: "r"(b) : "memory")
#define BAR_WAIT(b)   asm volatile("bar.sync %0, 64;"   :: "r"(b) : "memory")

// Compile-time producer batch: CNT<=16 rows starting at S0. Front-batched
// LDGs (constant indices -> full MLP), then coefficient math + STS.
template <int S0, int CNT>
__device__ __forceinline__ void produce(const float4* __restrict__ noise4,
                                        float4* __restrict__ s_uvrs,
                                        int nl, bool act, float4 wb,
                                        float c0, float c1, float c2, float c3,
                                        float xv, int lane) {
    float4 nb[CNT];
#pragma unroll
    for (int i = 0; i < CNT; ++i)
        nb[i] = noise4[(S0 + i) * NLUT + nl];
#pragma unroll
    for (int i = 0; i < CNT; ++i) {
        const float4 n = nb[i];
        const float w0 = fmaf(c0, n.x, wb.x);
        const float w1 = fmaf(c1, n.y, wb.y);
        const float w2 = fmaf(c2, n.z, wb.z);
        const float w3 = fmaf(c3, n.w, wb.w);
        const float d01 = w1 - w0, d23 = w3 - w2;
        const float p01 = w0 + w1, p23 = w2 + w3;
        float4 q;
        q.x = act ? 0.25f * (d23 - d01) : 0.f;
        q.y = act ? 0.25f * (p23 - p01) : 0.f;
        q.z = act ? 0.25f * (d01 + d23) : 0.f;
        q.w = act ? 0.25f * (p01 + p23) : xv;
        s_uvrs[(S0 + i) * ROWS + lane] = q;
    }
}

__global__ void one_layer_net_kernel(const float* __restrict__ x,
                                     const float* __restrict__ weights,
                                     const float4* __restrict__ noise4,
                                     float* __restrict__ out) {
    extern __shared__ float4 s_uvrs[];   // [132][32] quadruples

    const int tid  = threadIdx.x;
    const int wrp  = tid >> 5;
    const int lane = tid & 31;

    if (wrp > 0) {
        // ------------------- PRODUCER WARPS (1..7), graded blocks ----------
        // w1: rows 0..5 (bar1) then 106..129 + pads (bar8)
        // w2: 6..13 (bar2)    w3: 14..25 (bar3)   w4: 26..41 (bar4)
        // w5: 42..61 (bar5)   w6: 62..81 (bar6)   w7: 82..105 (bar7)
        const bool act = (lane < NLUT);
        const int  nl  = act ? lane : 0;

        float4 wb = make_float4(0.f, 0.f, 0.f, 0.f);
        if (act) wb = reinterpret_cast<const float4*>(weights)[lane];
        const float c0 = fabsf(1.0f - fabsf(wb.x)) * 0.125f;
        const float c1 = fabsf(1.0f - fabsf(wb.y)) * 0.125f;
        const float c2 = fabsf(1.0f - fabsf(wb.z)) * 0.125f;
        const float c3 = fabsf(1.0f - fabsf(wb.w)) * 0.125f;
        const float xv = (lane == 27) ? x[0] : ((lane == 28) ? x[1] : 0.0f);

        int b;
        switch (wrp) {
        case 1:
            produce<0, 6>(noise4, s_uvrs, nl, act, wb, c0, c1, c2, c3, xv, lane);
            b = 1; BAR_ARRIVE(b);
            produce<106, 16>(noise4, s_uvrs, nl, act, wb, c0, c1, c2, c3, xv, lane);
            produce<122, 8>(noise4, s_uvrs, nl, act, wb, c0, c1, c2, c3, xv, lane);
            s_uvrs[130 * ROWS + lane] = make_float4(0.f, 0.f, 0.f, 0.f);
            s_uvrs[131 * ROWS + lane] = make_float4(0.f, 0.f, 0.f, 0.f);
            b = 8; BAR_ARRIVE(b);
            break;
        case 2:
            produce<6, 8>(noise4, s_uvrs, nl, act, wb, c0, c1, c2, c3, xv, lane);
            b = 2; BAR_ARRIVE(b);
            break;
        case 3:
            produce<14, 12>(noise4, s_uvrs, nl, act, wb, c0, c1, c2, c3, xv, lane);
            b = 3; BAR_ARRIVE(b);
            break;
        case 4:
            produce<26, 16>(noise4, s_uvrs, nl, act, wb, c0, c1, c2, c3, xv, lane);
            b = 4; BAR_ARRIVE(b);
            break;
        case 5:
            produce<42, 16>(noise4, s_uvrs, nl, act, wb, c0, c1, c2, c3, xv, lane);
            produce<58, 4>(noise4, s_uvrs, nl, act, wb, c0, c1, c2, c3, xv, lane);
            b = 5; BAR_ARRIVE(b);
            break;
        case 6:
            produce<62, 16>(noise4, s_uvrs, nl, act, wb, c0, c1, c2, c3, xv, lane);
            produce<78, 4>(noise4, s_uvrs, nl, act, wb, c0, c1, c2, c3, xv, lane);
            b = 6; BAR_ARRIVE(b);
            break;
        default:   // wrp == 7
            produce<82, 16>(noise4, s_uvrs, nl, act, wb, c0, c1, c2, c3, xv, lane);
            produce<98, 8>(noise4, s_uvrs, nl, act, wb, c0, c1, c2, c3, xv, lane);
            b = 7; BAR_ARRIVE(b);
            break;
        }
        return;
    }

    // ----------------------- CONSUMER WARP (0) — R7 2-step scan ------------
    const int sa = c_srcA[lane];
    const int sb = c_srcB[lane];
    const int aa = c_srcA[sa], ba = c_srcB[sa];
    const int ab = c_srcA[sb], bb = c_srcB[sb];

    float state = (lane < NLUT) ? -1.0f
                : (lane == 27) ? x[0]
                : (lane == 28) ? x[1] : 0.0f;

    int b = 1;
    BAR_WAIT(b);   // rows 0..5 ready

    const float4* pAp = s_uvrs + sa;
    const float4* pBp = s_uvrs + sb;
    const float4* pFp = s_uvrs + ROWS + lane;
    float4 cA = pAp[0];
    float4 cB = pBp[0];
    float4 cF = pFp[0];
    pAp += 2 * ROWS; pBp += 2 * ROWS; pFp += 2 * ROWS;

#define SCAN_ITER()                                                          \
    do {                                                                     \
        const float4 pA = pAp[0];                                            \
        const float4 pB = pBp[0];                                            \
        const float4 pF = pFp[0];                                            \
        pAp += 2 * ROWS; pBp += 2 * ROWS; pFp += 2 * ROWS;                   \
        const float aAv = __shfl_sync(0xFFFFFFFFu, state, aa);               \
        const float bAv = __shfl_sync(0xFFFFFFFFu, state, ba);               \
        const float aBv = __shfl_sync(0xFFFFFFFFu, state, ab);               \
        const float bBv = __shfl_sync(0xFFFFFFFFu, state, bb);               \
        const float iA = fmaf(bAv, fmaf(aAv, cA.x, cA.y),                    \
                              fmaf(aAv, cA.z, cA.w));                        \
        const float iB = fmaf(bBv, fmaf(aBv, cB.x, cB.y),                    \
                              fmaf(aBv, cB.z, cB.w));                        \
        state = fmaf(iB, fmaf(iA, cF.x, cF.y), fmaf(iA, cF.z, cF.w));        \
        cA = pA; cB = pB; cF = pF;                                           \
    } while (0)

    // iter k consumes rows 2k,2k+1, prefetches rows 2k+2,2k+3 (needs <=2k+3):
    //   k=0..1   <=5    (bar1, passed)    k=2..5   <=13   (bar2)
    //   k=6..11  <=25   (bar3)            k=12..19 <=41   (bar4)
    //   k=20..29 <=61   (bar5)            k=30..39 <=81   (bar6)
    //   k=40..51 <=105  (bar7)            k=52..64 <=131  (bar8)
    SCAN_ITER();
    SCAN_ITER();
    b = 2; BAR_WAIT(b);
#pragma unroll
    for (int i = 0; i < 4; ++i) SCAN_ITER();
    b = 3; BAR_WAIT(b);
#pragma unroll
    for (int i = 0; i < 6; ++i) SCAN_ITER();
    b = 4; BAR_WAIT(b);
#pragma unroll
    for (int i = 0; i < 8; ++i) SCAN_ITER();
    b = 5; BAR_WAIT(b);
#pragma unroll
    for (int i = 0; i < 10; ++i) SCAN_ITER();
    b = 6; BAR_WAIT(b);
#pragma unroll
    for (int i = 0; i < 10; ++i) SCAN_ITER();
    b = 7; BAR_WAIT(b);
#pragma unroll
    for (int i = 0; i < 12; ++i) SCAN_ITER();
    b = 8; BAR_WAIT(b);
#pragma unroll
    for (int i = 0; i < 13; ++i) SCAN_ITER();

    // Outputs: final[0,1] -> flat 1, final[1,2] -> flat 5, final[7,2] -> flat 23.
    if (lane == 1)  out[0] = state;
    if (lane == 5)  out[1] = state;
    if (lane == 23) out[2] = state;
}

extern "C" void kernel_launch(void* const* d_in, const int* in_sizes, int n_in,
                              void* d_out, int out_size) {
    (void)in_sizes; (void)n_in; (void)out_size;
    const float*  x  = (const float*)d_in[0];      // [2]
    const float*  w  = (const float*)d_in[1];      // [9,3,4]
    const float4* nz = (const float4*)d_in[2];     // [130,9,3,4] as float4
    float* out = (float*)d_out;                    // [3]

    const size_t smem = (size_t)UROWS * ROWS * sizeof(float4);   // 67584 B
    cudaFuncSetAttribute(one_layer_net_kernel,
                         cudaFuncAttributeMaxDynamicSharedMemorySize, (int)smem);
    one_layer_net_kernel<<<1, 256, smem>>>(x, w, nz, out);
}